// round 1
// baseline (speedup 1.0000x reference)
#include <cuda_runtime.h>
#include <math.h>

#define B_   8
#define N_   4096
#define H_   1024
#define H2_  512
#define NB_  128
#define M_   (B_*N_)          // 32768 tokens

// -------- scratch (device globals: allocation-free rule) --------
__device__ float g_h[(size_t)M_ * H2_];        // 64 MB  tanh(x@W1+b1)
__device__ float g_gate[M_];                   // gate logits
__device__ float g_pooled[(size_t)B_*NB_*H_];  // 4 MB
__device__ float g_y[(size_t)B_*NB_*H_];       // 4 MB  pooled@Wp+bp
__device__ float g_hasb[B_*NB_];

// ============================================================
// Kernel 1: h = tanh(X @ W1 + b1)   (32768x1024 @ 1024x512)
// classic 128x128x8 SGEMM, 256 threads, 8x8 per thread
// ============================================================
__global__ __launch_bounds__(256) void k_gemm1(const float* __restrict__ X,
                                               const float* __restrict__ W1,
                                               const float* __restrict__ b1) {
    __shared__ float As[8][128];
    __shared__ float Bs[8][128];
    const int tid = threadIdx.x;
    const int m0 = blockIdx.y * 128;
    const int n0 = blockIdx.x * 128;
    const int ty = tid >> 4, tx = tid & 15;

    float acc[8][8];
#pragma unroll
    for (int i = 0; i < 8; ++i)
#pragma unroll
        for (int j = 0; j < 8; ++j) acc[i][j] = 0.f;

    const int arow = tid >> 1;
    const int acg  = (tid & 1) * 4;
    const float* Ap = X + (size_t)(m0 + arow) * H_ + acg;
    const int brow = tid >> 5;
    const int bcol = (tid & 31) * 4;
    const float* Bp = W1 + (size_t)brow * H2_ + n0 + bcol;

    for (int k0 = 0; k0 < H_; k0 += 8) {
        float4 av = *(const float4*)(Ap + k0);
        float4 bv = *(const float4*)(Bp + (size_t)k0 * H2_);
        As[acg + 0][arow] = av.x;
        As[acg + 1][arow] = av.y;
        As[acg + 2][arow] = av.z;
        As[acg + 3][arow] = av.w;
        *(float4*)&Bs[brow][bcol] = bv;
        __syncthreads();
#pragma unroll
        for (int k = 0; k < 8; ++k) {
            float a[8], b[8];
            *(float4*)&a[0] = *(const float4*)&As[k][ty * 8];
            *(float4*)&a[4] = *(const float4*)&As[k][ty * 8 + 4];
            *(float4*)&b[0] = *(const float4*)&Bs[k][tx * 8];
            *(float4*)&b[4] = *(const float4*)&Bs[k][tx * 8 + 4];
#pragma unroll
            for (int i = 0; i < 8; ++i)
#pragma unroll
                for (int j = 0; j < 8; ++j) acc[i][j] += a[i] * b[j];
        }
        __syncthreads();
    }

    float bb[8];
#pragma unroll
    for (int j = 0; j < 8; ++j) bb[j] = b1[n0 + tx * 8 + j];
#pragma unroll
    for (int i = 0; i < 8; ++i) {
        const int row = m0 + ty * 8 + i;
        float4 o0, o1;
        o0.x = tanhf(acc[i][0] + bb[0]);
        o0.y = tanhf(acc[i][1] + bb[1]);
        o0.z = tanhf(acc[i][2] + bb[2]);
        o0.w = tanhf(acc[i][3] + bb[3]);
        o1.x = tanhf(acc[i][4] + bb[4]);
        o1.y = tanhf(acc[i][5] + bb[5]);
        o1.z = tanhf(acc[i][6] + bb[6]);
        o1.w = tanhf(acc[i][7] + bb[7]);
        float* dst = g_h + (size_t)row * H2_ + n0 + tx * 8;
        *(float4*)dst       = o0;
        *(float4*)(dst + 4) = o1;
    }
}

// ============================================================
// Kernel 2: gate = h @ W2 + b2    (one warp per token row)
// ============================================================
__global__ __launch_bounds__(256) void k_gate(const float* __restrict__ W2,
                                              const float* __restrict__ b2) {
    const int warp = threadIdx.x >> 5, lane = threadIdx.x & 31;
    const int row = blockIdx.x * 8 + warp;
    const float4* hp = (const float4*)(g_h + (size_t)row * H2_);
    const float4* wp = (const float4*)W2;
    float s = 0.f;
#pragma unroll
    for (int i = lane; i < H2_ / 4; i += 32) {
        float4 h4 = hp[i], w4 = wp[i];
        s += h4.x * w4.x + h4.y * w4.y + h4.z * w4.z + h4.w * w4.w;
    }
#pragma unroll
    for (int off = 16; off > 0; off >>= 1)
        s += __shfl_xor_sync(0xFFFFFFFFu, s, off);
    if (lane == 0) g_gate[row] = s + b2[0];
}

// ============================================================
// Kernel 3: per-(b,block) masked softmax + ct-mod + pooling
// grid (NB, B), 256 threads
// ============================================================
__global__ __launch_bounds__(256) void k_pool(const float* __restrict__ X,
                                              const int* __restrict__ bids,
                                              const unsigned char* __restrict__ pad,
                                              const int* __restrict__ ctype,
                                              const float* __restrict__ ct_emb) {
    const int b = blockIdx.y, k = blockIdx.x;
    const int tid = threadIdx.x;
    __shared__ int   s_idx[N_];
    __shared__ float s_w[N_];
    __shared__ float red[256];
    __shared__ int   s_cnt;
    if (tid == 0) s_cnt = 0;
    const int base = b * N_;

    // pass 1: max over member tokens
    float mx = -INFINITY;
    for (int n = tid; n < N_; n += 256) {
        if (bids[base + n] == k && pad[base + n] == 0)
            mx = fmaxf(mx, g_gate[base + n]);
    }
    red[tid] = mx;
    __syncthreads();
    for (int st = 128; st; st >>= 1) {
        if (tid < st) red[tid] = fmaxf(red[tid], red[tid + st]);
        __syncthreads();
    }
    float m = red[0];
    __syncthreads();
    if (!isfinite(m)) m = 0.f;   // empty block

    // pass 2: exp + compact member list + partial sum
    float se = 0.f;
    for (int n = tid; n < N_; n += 256) {
        if (bids[base + n] == k && pad[base + n] == 0) {
            float e = expf(g_gate[base + n] - m);
            se += e;
            int p = atomicAdd(&s_cnt, 1);
            s_idx[p] = n;
            s_w[p]   = e;
        }
    }
    red[tid] = se;
    __syncthreads();
    for (int st = 128; st; st >>= 1) {
        if (tid < st) red[tid] += red[tid + st];
        __syncthreads();
    }
    const float denom = red[0];
    __syncthreads();

    const float factor = 1.f + 0.1f * ct_emb[ctype[b] * NB_ + k];
    const float inv = (denom > 0.f) ? factor / fmaxf(denom, 1e-30f) : 0.f;
    const int cnt = s_cnt;

    // pass 3: pooled[b,k,:] = sum_i w_i * x[b, n_i, :]
    float a0 = 0.f, a1 = 0.f, a2 = 0.f, a3 = 0.f;
    for (int i = 0; i < cnt; ++i) {
        const float w = s_w[i] * inv;
        const float* xr = X + ((size_t)base + s_idx[i]) * H_;
        a0 += w * xr[tid];
        a1 += w * xr[tid + 256];
        a2 += w * xr[tid + 512];
        a3 += w * xr[tid + 768];
    }
    float* pr = g_pooled + (size_t)(b * NB_ + k) * H_;
    pr[tid]       = a0;
    pr[tid + 256] = a1;
    pr[tid + 512] = a2;
    pr[tid + 768] = a3;
    if (tid == 0) g_hasb[b * NB_ + k] = (cnt > 0) ? 1.f : 0.f;
}

// ============================================================
// Kernel 4: y = pooled @ Wp + bp   (1024x1024x1024)
// 64x64x16 SGEMM, 256 threads, 4x4 per thread (256 CTAs)
// ============================================================
__global__ __launch_bounds__(256) void k_gemm2(const float* __restrict__ Wp,
                                               const float* __restrict__ bp) {
    __shared__ float As[16][64];
    __shared__ float Bs[16][64];
    const int tid = threadIdx.x;
    const int m0 = blockIdx.y * 64;
    const int n0 = blockIdx.x * 64;
    const int ty = tid >> 4, tx = tid & 15;

    float acc[4][4];
#pragma unroll
    for (int i = 0; i < 4; ++i)
#pragma unroll
        for (int j = 0; j < 4; ++j) acc[i][j] = 0.f;

    const int arow = tid >> 2;
    const int acg  = (tid & 3) * 4;
    const float* Ap = g_pooled + (size_t)(m0 + arow) * H_ + acg;
    const int brow = tid >> 4;
    const int bcol = (tid & 15) * 4;
    const float* Bp = Wp + (size_t)brow * H_ + n0 + bcol;

    for (int k0 = 0; k0 < H_; k0 += 16) {
        float4 av = *(const float4*)(Ap + k0);
        float4 bv = *(const float4*)(Bp + (size_t)k0 * H_);
        As[acg + 0][arow] = av.x;
        As[acg + 1][arow] = av.y;
        As[acg + 2][arow] = av.z;
        As[acg + 3][arow] = av.w;
        *(float4*)&Bs[brow][bcol] = bv;
        __syncthreads();
#pragma unroll
        for (int k = 0; k < 16; ++k) {
            float a[4], b[4];
            *(float4*)&a[0] = *(const float4*)&As[k][ty * 4];
            *(float4*)&b[0] = *(const float4*)&Bs[k][tx * 4];
#pragma unroll
            for (int i = 0; i < 4; ++i)
#pragma unroll
                for (int j = 0; j < 4; ++j) acc[i][j] += a[i] * b[j];
        }
        __syncthreads();
    }

#pragma unroll
    for (int i = 0; i < 4; ++i) {
        const int row = m0 + ty * 4 + i;
        float4 o;
        o.x = acc[i][0] + bp[n0 + tx * 4 + 0];
        o.y = acc[i][1] + bp[n0 + tx * 4 + 1];
        o.z = acc[i][2] + bp[n0 + tx * 4 + 2];
        o.w = acc[i][3] + bp[n0 + tx * 4 + 3];
        *(float4*)&g_y[(size_t)row * H_ + n0 + tx * 4] = o;
    }
}

// ============================================================
// Kernel 5: LayerNorm + ELU + present mask, write d_out (+ has_b)
// one CTA per (b,k) row, 256 threads (4 floats each)
// ============================================================
__global__ __launch_bounds__(256) void k_ln(const float* __restrict__ ln_g,
                                            const float* __restrict__ ln_b,
                                            float* __restrict__ out,
                                            int out_size) {
    const int row = blockIdx.x;         // b*NB + k
    const int tid = threadIdx.x;
    __shared__ float red[256];
    __shared__ float sh_mu, sh_r;
    __shared__ int sh_present;

    float4 v = ((const float4*)(g_y + (size_t)row * H_))[tid];
    float s = v.x + v.y + v.z + v.w;
    red[tid] = s;
    __syncthreads();
    for (int st = 128; st; st >>= 1) {
        if (tid < st) red[tid] += red[tid + st];
        __syncthreads();
    }
    if (tid == 0) sh_mu = red[0] * (1.f / H_);
    __syncthreads();
    const float mu = sh_mu;
    const float dx = v.x - mu, dy = v.y - mu, dz = v.z - mu, dw = v.w - mu;
    red[tid] = dx * dx + dy * dy + dz * dz + dw * dw;
    __syncthreads();
    for (int st = 128; st; st >>= 1) {
        if (tid < st) red[tid] += red[tid + st];
        __syncthreads();
    }
    if (tid == 0) {
        sh_r = rsqrtf(red[0] * (1.f / H_) + 1e-5f);
        const int k = row & (NB_ - 1);
        int p = 0;
        for (int bb = 0; bb < B_; ++bb) p |= (g_hasb[bb * NB_ + k] != 0.f);
        sh_present = p;
    }
    __syncthreads();
    const float r = sh_r;
    const int present = sh_present;

    float4 g = ((const float4*)ln_g)[tid];
    float4 be = ((const float4*)ln_b)[tid];
    float4 o;
    o.x = dx * r * g.x + be.x;
    o.y = dy * r * g.y + be.y;
    o.z = dz * r * g.z + be.z;
    o.w = dw * r * g.w + be.w;
    o.x = (o.x > 0.f) ? o.x : expm1f(o.x);
    o.y = (o.y > 0.f) ? o.y : expm1f(o.y);
    o.z = (o.z > 0.f) ? o.z : expm1f(o.z);
    o.w = (o.w > 0.f) ? o.w : expm1f(o.w);
    if (!present) { o.x = 0.f; o.y = 0.f; o.z = 0.f; o.w = 0.f; }
    ((float4*)(out + (size_t)row * H_))[tid] = o;

    if (tid == 0 && out_size >= B_ * NB_ * H_ + B_ * NB_)
        out[B_ * NB_ * H_ + row] = g_hasb[row];
}

// ============================================================
extern "C" void kernel_launch(void* const* d_in, const int* in_sizes, int n_in,
                              void* d_out, int out_size) {
    const float* x       = (const float*)d_in[0];
    const int*   ctype   = (const int*)d_in[1];
    const int*   bids    = (const int*)d_in[2];
    const unsigned char* pad = (const unsigned char*)d_in[3];
    const float* W1      = (const float*)d_in[4];
    const float* b1      = (const float*)d_in[5];
    const float* W2      = (const float*)d_in[6];
    const float* b2      = (const float*)d_in[7];
    const float* ct_emb  = (const float*)d_in[8];
    const float* Wp      = (const float*)d_in[9];
    const float* bp      = (const float*)d_in[10];
    const float* ln_g    = (const float*)d_in[11];
    const float* ln_b    = (const float*)d_in[12];
    float* out = (float*)d_out;

    k_gemm1<<<dim3(H2_ / 128, M_ / 128), 256>>>(x, W1, b1);
    k_gate<<<M_ / 8, 256>>>(W2, b2);
    k_pool<<<dim3(NB_, B_), 256>>>(x, bids, pad, ctype, ct_emb);
    k_gemm2<<<dim3(H_ / 64, (B_ * NB_) / 64), 256>>>(Wp, bp);
    k_ln<<<B_ * NB_, 256>>>(ln_g, ln_b, out, out_size);
}

// round 9
// speedup vs baseline: 2.3501x; 2.3501x over previous
#include <cuda_runtime.h>
#include <cuda_bf16.h>
#include <cstdint>
#include <math.h>

#define B_   8
#define N_   4096
#define H_   1024
#define H2_  512
#define NB_  128
#define M_   (B_*N_)          // 32768 tokens

typedef __nv_bfloat16 bf16;

// -------- scratch (device globals: allocation-free rule) --------
__device__ float g_gate[M_];
__device__ float g_gpart[4][M_];                 // per-column-CTA gate partials
__device__ float g_pooled[(size_t)B_*NB_*H_];    // 4 MB
__device__ float g_y[(size_t)B_*NB_*H_];         // 4 MB
__device__ float g_hasb[B_*NB_];

__device__ bf16 g_ahi[(size_t)M_ * H_];          // 64 MB
__device__ bf16 g_alo[(size_t)M_ * H_];          // 64 MB
__device__ bf16 g_w1hi[(size_t)H2_ * H_];        // 1 MB  (W1^T split)
__device__ bf16 g_w1lo[(size_t)H2_ * H_];
__device__ bf16 g_phi[(size_t)B_*NB_ * H_];      // 2 MB  (pooled split)
__device__ bf16 g_plo[(size_t)B_*NB_ * H_];
__device__ bf16 g_wphi[(size_t)H_ * H_];         // 2 MB  (Wp^T split)
__device__ bf16 g_wplo[(size_t)H_ * H_];

// ============================================================
// PTX helpers (all sm_80-compatible; NO tcgen05 — ptxas targets sm_103)
// ============================================================
__device__ __forceinline__ uint32_t smem_u32(const void* p) {
    uint32_t a;
    asm("{ .reg .u64 t; cvta.to.shared.u64 t, %1; cvt.u32.u64 %0, t; }" : "=r"(a) : "l"(p));
    return a;
}
#define SWZ(o) ((o) ^ (((o) >> 3) & 0x70))

__device__ __forceinline__ void cp_async16(uint32_t saddr, const void* gaddr) {
    asm volatile("cp.async.cg.shared.global [%0], [%1], 16;" :: "r"(saddr), "l"(gaddr));
}
#define CP_COMMIT() asm volatile("cp.async.commit_group;" ::: "memory")

__device__ __forceinline__ void ldsm4(uint32_t* r, uint32_t a) {
    asm volatile("ldmatrix.sync.aligned.m8n8.x4.shared.b16 {%0,%1,%2,%3}, [%4];"
                 : "=r"(r[0]), "=r"(r[1]), "=r"(r[2]), "=r"(r[3]) : "r"(a));
}
__device__ __forceinline__ void ldsm2(uint32_t* r, uint32_t a) {
    asm volatile("ldmatrix.sync.aligned.m8n8.x2.shared.b16 {%0,%1}, [%2];"
                 : "=r"(r[0]), "=r"(r[1]) : "r"(a));
}
__device__ __forceinline__ void mma16816(float* c, const uint32_t* a, const uint32_t* b) {
    asm volatile(
        "mma.sync.aligned.m16n8k16.row.col.f32.bf16.bf16.f32 "
        "{%0,%1,%2,%3}, {%4,%5,%6,%7}, {%8,%9}, {%0,%1,%2,%3};"
        : "+f"(c[0]), "+f"(c[1]), "+f"(c[2]), "+f"(c[3])
        : "r"(a[0]), "r"(a[1]), "r"(a[2]), "r"(a[3]), "r"(b[0]), "r"(b[1]));
}

// ============================================================
// Conversion kernels (fp32 -> bf16 hi/lo split)
// ============================================================
__global__ __launch_bounds__(256) void k_split_a(const float* __restrict__ X,
                                                 bf16* __restrict__ hi,
                                                 bf16* __restrict__ lo) {
    size_t i = (size_t)blockIdx.x * 256 + threadIdx.x;   // float4 index
    float4 v = ((const float4*)X)[i];
    bf16 hx = __float2bfloat16(v.x), hy = __float2bfloat16(v.y);
    bf16 hz = __float2bfloat16(v.z), hw = __float2bfloat16(v.w);
    bf16 lx = __float2bfloat16(v.x - __bfloat162float(hx));
    bf16 ly = __float2bfloat16(v.y - __bfloat162float(hy));
    bf16 lz = __float2bfloat16(v.z - __bfloat162float(hz));
    bf16 lw = __float2bfloat16(v.w - __bfloat162float(hw));
    __nv_bfloat162 h0 = {hx, hy}, h1 = {hz, hw};
    __nv_bfloat162 l0 = {lx, ly}, l1 = {lz, lw};
    uint2 hp = {*(uint32_t*)&h0, *(uint32_t*)&h1};
    uint2 lp = {*(uint32_t*)&l0, *(uint32_t*)&l1};
    ((uint2*)hi)[i] = hp;
    ((uint2*)lo)[i] = lp;
}

// W [K x Nn] row-major -> T [Nn x K] bf16 hi/lo (transpose + split)
__global__ __launch_bounds__(256) void k_split_wt(const float* __restrict__ W,
                                                  bf16* __restrict__ Thi,
                                                  bf16* __restrict__ Tlo,
                                                  int K, int Nn) {
    __shared__ float t[32][33];
    const int k0 = blockIdx.x * 32, n0 = blockIdx.y * 32;
    const int tx = threadIdx.x & 31, ty = threadIdx.x >> 5;  // 32 x 8
#pragma unroll
    for (int i = 0; i < 32; i += 8)
        t[ty + i][tx] = W[(size_t)(k0 + ty + i) * Nn + n0 + tx];
    __syncthreads();
#pragma unroll
    for (int i = 0; i < 32; i += 8) {
        float v = t[tx][ty + i];
        bf16 h = __float2bfloat16(v);
        bf16 l = __float2bfloat16(v - __bfloat162float(h));
        size_t o = (size_t)(n0 + ty + i) * K + k0 + tx;
        Thi[o] = h;
        Tlo[o] = l;
    }
}

// ============================================================
// mma.sync bf16 split GEMM: C[M x Nout] = A @ B^T  (3-term hi/lo split)
// CTA 128x128, K-chunk 32, smem rows = [hi 64B | lo 64B] SW128, 3-stage cp.async
// EPI 0: gate fusion  -> gpart[cta_n][m] = sum_n tanh(acc+b1[n])*W2[n]
// EPI 1: out = acc + bias
// ============================================================
#define STG_BYTES 32768
#define NSTAGE    3
#define SMEM_DYN  (NSTAGE * STG_BYTES + 1024)

template <int EPI>
__global__ __launch_bounds__(256) void k_mma(const bf16* __restrict__ Ahi,
                                             const bf16* __restrict__ Alo,
                                             const bf16* __restrict__ Bhi,
                                             const bf16* __restrict__ Blo,
                                             const float* __restrict__ bias,
                                             const float* __restrict__ w2,
                                             float* __restrict__ out,
                                             float* __restrict__ gpart,
                                             int Ktot, int Nout) {
    extern __shared__ char smem_raw[];
    const int tid = threadIdx.x;
    const int wid = tid >> 5, lane = tid & 31;
    const int mw = wid & 1, nw = wid >> 1;        // 2 x 4 warp grid
    const int m0 = blockIdx.y * 128;
    const int n0 = blockIdx.x * 128;
    const uint32_t sbase = (smem_u32(smem_raw) + 1023u) & ~1023u;
    const int NC = Ktot >> 5;                     // K-chunks of 32

    float C[4][4][4];
#pragma unroll
    for (int mi = 0; mi < 4; ++mi)
#pragma unroll
        for (int ni = 0; ni < 4; ++ni)
#pragma unroll
            for (int q = 0; q < 4; ++q) C[mi][ni][q] = 0.f;

    auto load_chunk = [&](int c, int st) {
        const uint32_t sa = sbase + (uint32_t)st * STG_BYTES;
        const int k0 = c * 32;
#pragma unroll
        for (int i = 0; i < 4; ++i) {
            int id = tid + i * 256;
            int r = id >> 3, rem = id & 7, half = rem >> 2, g = rem & 3;
            uint32_t off = (uint32_t)(r * 128 + half * 64 + g * 16);
            const bf16* srcA = half ? Alo : Ahi;
            cp_async16(sa + SWZ(off), srcA + (size_t)(m0 + r) * Ktot + k0 + g * 8);
            const bf16* srcB = half ? Blo : Bhi;
            cp_async16(sa + 16384u + SWZ(off), srcB + (size_t)(n0 + r) * Ktot + k0 + g * 8);
        }
        CP_COMMIT();
    };

    auto compute = [&](int st) {
        const uint32_t sa = sbase + (uint32_t)st * STG_BYTES;
        const uint32_t sbt = sa + 16384u;
#pragma unroll
        for (int kb = 0; kb < 32; kb += 16) {
            uint32_t Af[4][2][4];
#pragma unroll
            for (int mi = 0; mi < 4; ++mi)
#pragma unroll
                for (int h = 0; h < 2; ++h) {
                    int row = mw * 64 + mi * 16 + (lane & 15);
                    uint32_t coln = (uint32_t)(h * 64 + (kb + (lane >> 4) * 8) * 2);
                    ldsm4(Af[mi][h], sa + row * 128 + (coln ^ ((row & 7) << 4)));
                }
            uint32_t Bf[4][2][2];
#pragma unroll
            for (int ni = 0; ni < 4; ++ni)
#pragma unroll
                for (int h = 0; h < 2; ++h) {
                    int row = nw * 32 + ni * 8 + (lane & 7);
                    uint32_t coln = (uint32_t)(h * 64 + (kb + ((lane >> 3) & 1) * 8) * 2);
                    ldsm2(Bf[ni][h], sbt + row * 128 + (coln ^ ((row & 7) << 4)));
                }
#pragma unroll
            for (int mi = 0; mi < 4; ++mi)
#pragma unroll
                for (int ni = 0; ni < 4; ++ni) {
                    mma16816(C[mi][ni], Af[mi][0], Bf[ni][0]);   // hi*hi
                    mma16816(C[mi][ni], Af[mi][0], Bf[ni][1]);   // hi*lo
                    mma16816(C[mi][ni], Af[mi][1], Bf[ni][0]);   // lo*hi
                }
        }
    };

    load_chunk(0, 0);
    load_chunk(1, 1);
    load_chunk(2, 2);

    for (int c = 0; c < NC; ++c) {
        const int pend = (c + 2 <= NC - 1) ? 2 : (c + 1 <= NC - 1) ? 1 : 0;
        if (pend == 2)      asm volatile("cp.async.wait_group 2;" ::: "memory");
        else if (pend == 1) asm volatile("cp.async.wait_group 1;" ::: "memory");
        else                asm volatile("cp.async.wait_group 0;" ::: "memory");
        __syncthreads();
        compute(c % 3);
        __syncthreads();
        if (c + 3 < NC) load_chunk(c + 3, (c + 3) % 3);
    }

    if (EPI == 0) {
        // gate fusion: per-row partial dot of tanh(acc+b1) with W2
        float* gp = (float*)smem_raw;     // [4][128], pipeline smem is done
        const int cbase = n0 + nw * 32 + 2 * (lane & 3);
        float w2v[4][2], b1v[4][2];
#pragma unroll
        for (int ni = 0; ni < 4; ++ni) {
            w2v[ni][0] = w2[cbase + ni * 8];
            w2v[ni][1] = w2[cbase + ni * 8 + 1];
            b1v[ni][0] = bias[cbase + ni * 8];
            b1v[ni][1] = bias[cbase + ni * 8 + 1];
        }
#pragma unroll
        for (int mi = 0; mi < 4; ++mi) {
            float a = 0.f, b = 0.f;
#pragma unroll
            for (int ni = 0; ni < 4; ++ni) {
                a += tanhf(C[mi][ni][0] + b1v[ni][0]) * w2v[ni][0];
                a += tanhf(C[mi][ni][1] + b1v[ni][1]) * w2v[ni][1];
                b += tanhf(C[mi][ni][2] + b1v[ni][0]) * w2v[ni][0];
                b += tanhf(C[mi][ni][3] + b1v[ni][1]) * w2v[ni][1];
            }
            a += __shfl_xor_sync(0xFFFFFFFFu, a, 1);
            a += __shfl_xor_sync(0xFFFFFFFFu, a, 2);
            b += __shfl_xor_sync(0xFFFFFFFFu, b, 1);
            b += __shfl_xor_sync(0xFFFFFFFFu, b, 2);
            if ((lane & 3) == 0) {
                int ml = mw * 64 + mi * 16 + (lane >> 2);
                gp[nw * 128 + ml]     = a;
                gp[nw * 128 + ml + 8] = b;
            }
        }
        __syncthreads();
        if (tid < 128) {
            float s = gp[tid] + gp[128 + tid] + gp[256 + tid] + gp[384 + tid];
            gpart[(size_t)blockIdx.x * M_ + m0 + tid] = s;
        }
    } else {
        // plain bias epilogue -> out
#pragma unroll
        for (int mi = 0; mi < 4; ++mi) {
            const int row = m0 + mw * 64 + mi * 16 + (lane >> 2);
#pragma unroll
            for (int ni = 0; ni < 4; ++ni) {
                const int col = n0 + nw * 32 + ni * 8 + 2 * (lane & 3);
                float2 v0 = {C[mi][ni][0] + bias[col], C[mi][ni][1] + bias[col + 1]};
                float2 v1 = {C[mi][ni][2] + bias[col], C[mi][ni][3] + bias[col + 1]};
                *(float2*)&out[(size_t)row * Nout + col]       = v0;
                *(float2*)&out[(size_t)(row + 8) * Nout + col] = v1;
            }
        }
    }
}

// ============================================================
// gate final reduce: gate[m] = sum of 4 column partials + b2
// ============================================================
__global__ __launch_bounds__(256) void k_gate_final(const float* __restrict__ b2) {
    const int m = blockIdx.x * 256 + threadIdx.x;
    g_gate[m] = g_gpart[0][m] + g_gpart[1][m] + g_gpart[2][m] + g_gpart[3][m] + b2[0];
}

// ============================================================
// per-(b,block) masked softmax + ct-mod + pooling
// ============================================================
__global__ __launch_bounds__(256) void k_pool(const float* __restrict__ X,
                                              const int* __restrict__ bids,
                                              const unsigned char* __restrict__ pad,
                                              const int* __restrict__ ctype,
                                              const float* __restrict__ ct_emb) {
    const int b = blockIdx.y, k = blockIdx.x;
    const int tid = threadIdx.x;
    __shared__ int   s_idx[N_];
    __shared__ float s_w[N_];
    __shared__ float red[256];
    __shared__ int   s_cnt;
    if (tid == 0) s_cnt = 0;
    const int base = b * N_;

    float mx = -INFINITY;
    for (int n = tid; n < N_; n += 256) {
        if (bids[base + n] == k && pad[base + n] == 0)
            mx = fmaxf(mx, g_gate[base + n]);
    }
    red[tid] = mx;
    __syncthreads();
    for (int st = 128; st; st >>= 1) {
        if (tid < st) red[tid] = fmaxf(red[tid], red[tid + st]);
        __syncthreads();
    }
    float m = red[0];
    __syncthreads();
    if (!isfinite(m)) m = 0.f;

    float se = 0.f;
    for (int n = tid; n < N_; n += 256) {
        if (bids[base + n] == k && pad[base + n] == 0) {
            float e = expf(g_gate[base + n] - m);
            se += e;
            int p = atomicAdd(&s_cnt, 1);
            s_idx[p] = n;
            s_w[p]   = e;
        }
    }
    red[tid] = se;
    __syncthreads();
    for (int st = 128; st; st >>= 1) {
        if (tid < st) red[tid] += red[tid + st];
        __syncthreads();
    }
    const float denom = red[0];
    __syncthreads();

    const float factor = 1.f + 0.1f * ct_emb[ctype[b] * NB_ + k];
    const float inv = (denom > 0.f) ? factor / fmaxf(denom, 1e-30f) : 0.f;
    const int cnt = s_cnt;

    float a0 = 0.f, a1 = 0.f, a2 = 0.f, a3 = 0.f;
    for (int i = 0; i < cnt; ++i) {
        const float w = s_w[i] * inv;
        const float* xr = X + ((size_t)base + s_idx[i]) * H_;
        a0 += w * xr[tid];
        a1 += w * xr[tid + 256];
        a2 += w * xr[tid + 512];
        a3 += w * xr[tid + 768];
    }
    float* pr = g_pooled + (size_t)(b * NB_ + k) * H_;
    pr[tid]       = a0;
    pr[tid + 256] = a1;
    pr[tid + 512] = a2;
    pr[tid + 768] = a3;
    if (tid == 0) g_hasb[b * NB_ + k] = (cnt > 0) ? 1.f : 0.f;
}

// ============================================================
// LayerNorm + ELU + present mask
// ============================================================
__global__ __launch_bounds__(256) void k_ln(const float* __restrict__ ln_g,
                                            const float* __restrict__ ln_b,
                                            float* __restrict__ out,
                                            int out_size) {
    const int row = blockIdx.x;
    const int tid = threadIdx.x;
    __shared__ float red[256];
    __shared__ float sh_mu, sh_r;
    __shared__ int sh_present;

    float4 v = ((const float4*)(g_y + (size_t)row * H_))[tid];
    red[tid] = v.x + v.y + v.z + v.w;
    __syncthreads();
    for (int st = 128; st; st >>= 1) {
        if (tid < st) red[tid] += red[tid + st];
        __syncthreads();
    }
    if (tid == 0) sh_mu = red[0] * (1.f / H_);
    __syncthreads();
    const float mu = sh_mu;
    const float dx = v.x - mu, dy = v.y - mu, dz = v.z - mu, dw = v.w - mu;
    red[tid] = dx * dx + dy * dy + dz * dz + dw * dw;
    __syncthreads();
    for (int st = 128; st; st >>= 1) {
        if (tid < st) red[tid] += red[tid + st];
        __syncthreads();
    }
    if (tid == 0) {
        sh_r = rsqrtf(red[0] * (1.f / H_) + 1e-5f);
        const int k = row & (NB_ - 1);
        int p = 0;
        for (int bb = 0; bb < B_; ++bb) p |= (g_hasb[bb * NB_ + k] != 0.f);
        sh_present = p;
    }
    __syncthreads();
    const float r = sh_r;
    const int present = sh_present;

    float4 g = ((const float4*)ln_g)[tid];
    float4 be = ((const float4*)ln_b)[tid];
    float4 o;
    o.x = dx * r * g.x + be.x;
    o.y = dy * r * g.y + be.y;
    o.z = dz * r * g.z + be.z;
    o.w = dw * r * g.w + be.w;
    o.x = (o.x > 0.f) ? o.x : expm1f(o.x);
    o.y = (o.y > 0.f) ? o.y : expm1f(o.y);
    o.z = (o.z > 0.f) ? o.z : expm1f(o.z);
    o.w = (o.w > 0.f) ? o.w : expm1f(o.w);
    if (!present) { o.x = 0.f; o.y = 0.f; o.z = 0.f; o.w = 0.f; }
    ((float4*)(out + (size_t)row * H_))[tid] = o;

    if (tid == 0 && out_size >= B_ * NB_ * H_ + B_ * NB_)
        out[B_ * NB_ * H_ + row] = g_hasb[row];
}

// ============================================================
extern "C" void kernel_launch(void* const* d_in, const int* in_sizes, int n_in,
                              void* d_out, int out_size) {
    const float* x       = (const float*)d_in[0];
    const int*   ctype   = (const int*)d_in[1];
    const int*   bids    = (const int*)d_in[2];
    const unsigned char* pad = (const unsigned char*)d_in[3];
    const float* W1      = (const float*)d_in[4];
    const float* b1      = (const float*)d_in[5];
    const float* W2      = (const float*)d_in[6];
    const float* b2      = (const float*)d_in[7];
    const float* ct_emb  = (const float*)d_in[8];
    const float* Wp      = (const float*)d_in[9];
    const float* bp      = (const float*)d_in[10];
    const float* ln_g    = (const float*)d_in[11];
    const float* ln_b    = (const float*)d_in[12];
    float* out = (float*)d_out;

    cudaFuncSetAttribute(k_mma<0>, cudaFuncAttributeMaxDynamicSharedMemorySize, SMEM_DYN);
    cudaFuncSetAttribute(k_mma<1>, cudaFuncAttributeMaxDynamicSharedMemorySize, SMEM_DYN);

    bf16 *ahi, *alo, *w1hi, *w1lo, *phi, *plo, *wphi, *wplo;
    float *pooled, *ybuf, *gpart;
    cudaGetSymbolAddress((void**)&ahi,  g_ahi);
    cudaGetSymbolAddress((void**)&alo,  g_alo);
    cudaGetSymbolAddress((void**)&w1hi, g_w1hi);
    cudaGetSymbolAddress((void**)&w1lo, g_w1lo);
    cudaGetSymbolAddress((void**)&phi,  g_phi);
    cudaGetSymbolAddress((void**)&plo,  g_plo);
    cudaGetSymbolAddress((void**)&wphi, g_wphi);
    cudaGetSymbolAddress((void**)&wplo, g_wplo);
    cudaGetSymbolAddress((void**)&pooled, g_pooled);
    cudaGetSymbolAddress((void**)&ybuf, g_y);
    cudaGetSymbolAddress((void**)&gpart, g_gpart);

    // gate MLP: gemm1 with fused tanh + W2 dot (h never materialized)
    k_split_a<<<(size_t)M_ * H_ / 4 / 256, 256>>>(x, ahi, alo);
    k_split_wt<<<dim3(H_ / 32, H2_ / 32), 256>>>(W1, w1hi, w1lo, H_, H2_);
    k_mma<0><<<dim3(H2_ / 128, M_ / 128), 256, SMEM_DYN>>>(
        ahi, alo, w1hi, w1lo, b1, W2, nullptr, gpart, H_, H2_);
    k_gate_final<<<M_ / 256, 256>>>(b2);
    // softmax + pooling
    k_pool<<<dim3(NB_, B_), 256>>>(x, bids, pad, ctype, ct_emb);
    // projection: pooled @ Wp + bp
    k_split_a<<<(size_t)B_ * NB_ * H_ / 4 / 256, 256>>>(pooled, phi, plo);
    k_split_wt<<<dim3(H_ / 32, H_ / 32), 256>>>(Wp, wphi, wplo, H_, H_);
    k_mma<1><<<dim3(H_ / 128, (B_ * NB_) / 128), 256, SMEM_DYN>>>(
        phi, plo, wphi, wplo, bp, nullptr, ybuf, nullptr, H_, H_);
    // LN + ELU
    k_ln<<<B_ * NB_, 256>>>(ln_g, ln_b, out, out_size);
}

// round 14
// speedup vs baseline: 3.0431x; 1.2949x over previous
#include <cuda_runtime.h>
#include <cuda_fp16.h>
#include <cstdint>
#include <math.h>

#define B_   8
#define N_   4096
#define H_   1024
#define H2_  512
#define NB_  128
#define M_   (B_*N_)          // 32768 tokens

typedef __half hf;

// -------- scratch (device globals: allocation-free rule) --------
__device__ float g_gate[M_];
__device__ float g_gpart[4][M_];                 // per-column-CTA gate partials
__device__ float g_pooled[(size_t)B_*NB_*H_];    // 4 MB
__device__ float g_y[(size_t)B_*NB_*H_];         // 4 MB
__device__ float g_hasb[B_*NB_];

__device__ hf g_ah[(size_t)M_ * H_];             // 64 MB  x as fp16 (hi only)
__device__ hf g_w1h[(size_t)H2_ * H_];           // 1 MB   W1^T hi
__device__ hf g_w1l[(size_t)H2_ * H_];           //        W1^T lo
__device__ hf g_ph[(size_t)B_*NB_ * H_];         // 2 MB   pooled fp16
__device__ hf g_wph[(size_t)H_ * H_];            // 2 MB   Wp^T hi
__device__ hf g_wpl[(size_t)H_ * H_];            //        Wp^T lo

// ============================================================
// PTX helpers (sm_80-compatible; ptxas targets plain sm_103)
// ============================================================
__device__ __forceinline__ uint32_t smem_u32(const void* p) {
    uint32_t a;
    asm("{ .reg .u64 t; cvta.to.shared.u64 t, %1; cvt.u32.u64 %0, t; }" : "=r"(a) : "l"(p));
    return a;
}
#define SWZ(o) ((o) ^ (((o) >> 3) & 0x70))

__device__ __forceinline__ void cp_async16(uint32_t saddr, const void* gaddr) {
    asm volatile("cp.async.cg.shared.global [%0], [%1], 16;" :: "r"(saddr), "l"(gaddr));
}
#define CP_COMMIT() asm volatile("cp.async.commit_group;" ::: "memory")

__device__ __forceinline__ void ldsm4(uint32_t* r, uint32_t a) {
    asm volatile("ldmatrix.sync.aligned.m8n8.x4.shared.b16 {%0,%1,%2,%3}, [%4];"
                 : "=r"(r[0]), "=r"(r[1]), "=r"(r[2]), "=r"(r[3]) : "r"(a));
}
__device__ __forceinline__ void ldsm2(uint32_t* r, uint32_t a) {
    asm volatile("ldmatrix.sync.aligned.m8n8.x2.shared.b16 {%0,%1}, [%2];"
                 : "=r"(r[0]), "=r"(r[1]) : "r"(a));
}
__device__ __forceinline__ void mma16816(float* c, const uint32_t* a, const uint32_t* b) {
    asm volatile(
        "mma.sync.aligned.m16n8k16.row.col.f32.f16.f16.f32 "
        "{%0,%1,%2,%3}, {%4,%5,%6,%7}, {%8,%9}, {%0,%1,%2,%3};"
        : "+f"(c[0]), "+f"(c[1]), "+f"(c[2]), "+f"(c[3])
        : "r"(a[0]), "r"(a[1]), "r"(a[2]), "r"(a[3]), "r"(b[0]), "r"(b[1]));
}

// ============================================================
// Conversion kernels
// ============================================================
// fp32 -> fp16 (hi only), vectorized
__global__ __launch_bounds__(256) void k_cvt_h(const float* __restrict__ X,
                                               hf* __restrict__ out) {
    size_t i = (size_t)blockIdx.x * 256 + threadIdx.x;   // float4 index
    float4 v = ((const float4*)X)[i];
    __half2 h0 = __floats2half2_rn(v.x, v.y);
    __half2 h1 = __floats2half2_rn(v.z, v.w);
    uint2 hp = {*(uint32_t*)&h0, *(uint32_t*)&h1};
    ((uint2*)out)[i] = hp;
}

// W [K x Nn] row-major -> T [Nn x K] fp16 hi/lo (transpose + split)
__global__ __launch_bounds__(256) void k_split_wt(const float* __restrict__ W,
                                                  hf* __restrict__ Thi,
                                                  hf* __restrict__ Tlo,
                                                  int K, int Nn) {
    __shared__ float t[32][33];
    const int k0 = blockIdx.x * 32, n0 = blockIdx.y * 32;
    const int tx = threadIdx.x & 31, ty = threadIdx.x >> 5;  // 32 x 8
#pragma unroll
    for (int i = 0; i < 32; i += 8)
        t[ty + i][tx] = W[(size_t)(k0 + ty + i) * Nn + n0 + tx];
    __syncthreads();
#pragma unroll
    for (int i = 0; i < 32; i += 8) {
        float v = t[tx][ty + i];
        hf h = __float2half_rn(v);
        hf l = __float2half_rn(v - __half2float(h));
        size_t o = (size_t)(n0 + ty + i) * K + k0 + tx;
        Thi[o] = h;
        Tlo[o] = l;
    }
}

// ============================================================
// mma.sync fp16 2-term GEMM: C[M x Nout] = A @ B^T ≈ Ah@Bh + Ah@Bl
// CTA 128x128, K-chunk 64, stage = A(16K)+Bhi(16K)+Blo(16K), 2-stage cp.async
// EPI 0: gate fusion  -> gpart[cta_n][m] = sum_n tanh(acc+b1[n])*W2[n]
// EPI 1: out = acc + bias
// ============================================================
#define STG_BYTES 49152
#define SMEM_DYN  (2 * STG_BYTES + 1024)

template <int EPI>
__global__ __launch_bounds__(256) void k_mma(const hf* __restrict__ Ah,
                                             const hf* __restrict__ Bh,
                                             const hf* __restrict__ Bl,
                                             const float* __restrict__ bias,
                                             const float* __restrict__ w2,
                                             float* __restrict__ out,
                                             float* __restrict__ gpart,
                                             int Ktot, int Nout) {
    extern __shared__ char smem_raw[];
    const int tid = threadIdx.x;
    const int wid = tid >> 5, lane = tid & 31;
    const int mw = wid & 1, nw = wid >> 1;        // 2 x 4 warp grid
    const int m0 = blockIdx.y * 128;
    const int n0 = blockIdx.x * 128;
    const uint32_t sbase = (smem_u32(smem_raw) + 1023u) & ~1023u;
    const int NC = Ktot >> 6;                     // K-chunks of 64

    float C[4][4][4];
#pragma unroll
    for (int mi = 0; mi < 4; ++mi)
#pragma unroll
        for (int ni = 0; ni < 4; ++ni)
#pragma unroll
            for (int q = 0; q < 4; ++q) C[mi][ni][q] = 0.f;

    // stage layout: A @ 0 (16KB), Bhi @ 16384, Blo @ 32768; rows = 128B (64 fp16)
    auto load_chunk = [&](int c, int st) {
        const uint32_t sa = sbase + (uint32_t)st * STG_BYTES;
        const int k0 = c * 64;
#pragma unroll
        for (int t = 0; t < 3; ++t) {
            const hf* src = (t == 0) ? Ah : (t == 1) ? Bh : Bl;
            const int row0 = (t == 0) ? m0 : n0;
#pragma unroll
            for (int i = 0; i < 4; ++i) {
                int id = tid + i * 256;           // 0..1023
                int r = id >> 3, g = id & 7;      // row, 16B group
                uint32_t off = (uint32_t)(r * 128 + g * 16);
                cp_async16(sa + (uint32_t)t * 16384u + SWZ(off),
                           src + (size_t)(row0 + r) * Ktot + k0 + g * 8);
            }
        }
        CP_COMMIT();
    };

    auto compute = [&](int st) {
        const uint32_t sa  = sbase + (uint32_t)st * STG_BYTES;
        const uint32_t sbh = sa + 16384u;
        const uint32_t sbl = sa + 32768u;
#pragma unroll
        for (int kb = 0; kb < 64; kb += 16) {
            uint32_t Af[4][4];
#pragma unroll
            for (int mi = 0; mi < 4; ++mi) {
                int row = mw * 64 + mi * 16 + (lane & 15);
                uint32_t coln = (uint32_t)((kb + (lane >> 4) * 8) * 2);
                ldsm4(Af[mi], sa + row * 128 + (coln ^ ((row & 7) << 4)));
            }
            uint32_t Bfh[4][2], Bfl[4][2];
#pragma unroll
            for (int ni = 0; ni < 4; ++ni) {
                int row = nw * 32 + ni * 8 + (lane & 7);
                uint32_t coln = (uint32_t)((kb + ((lane >> 3) & 1) * 8) * 2);
                uint32_t sw = coln ^ ((row & 7) << 4);
                ldsm2(Bfh[ni], sbh + row * 128 + sw);
                ldsm2(Bfl[ni], sbl + row * 128 + sw);
            }
#pragma unroll
            for (int mi = 0; mi < 4; ++mi)
#pragma unroll
                for (int ni = 0; ni < 4; ++ni) {
                    mma16816(C[mi][ni], Af[mi], Bfh[ni]);   // Ah*Bhi
                    mma16816(C[mi][ni], Af[mi], Bfl[ni]);   // Ah*Blo
                }
        }
    };

    load_chunk(0, 0);
    if (NC > 1) load_chunk(1, 1);

    for (int c = 0; c < NC; ++c) {
        if (c + 1 < NC) asm volatile("cp.async.wait_group 1;" ::: "memory");
        else            asm volatile("cp.async.wait_group 0;" ::: "memory");
        __syncthreads();
        compute(c & 1);
        __syncthreads();
        if (c + 2 < NC) load_chunk(c + 2, c & 1);
    }

    if (EPI == 0) {
        // gate fusion: per-row partial dot of tanh(acc+b1) with W2
        float* gp = (float*)smem_raw;     // [4][128], pipeline smem is done
        const int cbase = n0 + nw * 32 + 2 * (lane & 3);
        float w2v[4][2], b1v[4][2];
#pragma unroll
        for (int ni = 0; ni < 4; ++ni) {
            w2v[ni][0] = w2[cbase + ni * 8];
            w2v[ni][1] = w2[cbase + ni * 8 + 1];
            b1v[ni][0] = bias[cbase + ni * 8];
            b1v[ni][1] = bias[cbase + ni * 8 + 1];
        }
#pragma unroll
        for (int mi = 0; mi < 4; ++mi) {
            float a = 0.f, b = 0.f;
#pragma unroll
            for (int ni = 0; ni < 4; ++ni) {
                a += tanhf(C[mi][ni][0] + b1v[ni][0]) * w2v[ni][0];
                a += tanhf(C[mi][ni][1] + b1v[ni][1]) * w2v[ni][1];
                b += tanhf(C[mi][ni][2] + b1v[ni][0]) * w2v[ni][0];
                b += tanhf(C[mi][ni][3] + b1v[ni][1]) * w2v[ni][1];
            }
            a += __shfl_xor_sync(0xFFFFFFFFu, a, 1);
            a += __shfl_xor_sync(0xFFFFFFFFu, a, 2);
            b += __shfl_xor_sync(0xFFFFFFFFu, b, 1);
            b += __shfl_xor_sync(0xFFFFFFFFu, b, 2);
            if ((lane & 3) == 0) {
                int ml = mw * 64 + mi * 16 + (lane >> 2);
                gp[nw * 128 + ml]     = a;
                gp[nw * 128 + ml + 8] = b;
            }
        }
        __syncthreads();
        if (tid < 128) {
            float s = gp[tid] + gp[128 + tid] + gp[256 + tid] + gp[384 + tid];
            gpart[(size_t)blockIdx.x * M_ + m0 + tid] = s;
        }
    } else {
        // plain bias epilogue -> out
#pragma unroll
        for (int mi = 0; mi < 4; ++mi) {
            const int row = m0 + mw * 64 + mi * 16 + (lane >> 2);
#pragma unroll
            for (int ni = 0; ni < 4; ++ni) {
                const int col = n0 + nw * 32 + ni * 8 + 2 * (lane & 3);
                float2 v0 = {C[mi][ni][0] + bias[col], C[mi][ni][1] + bias[col + 1]};
                float2 v1 = {C[mi][ni][2] + bias[col], C[mi][ni][3] + bias[col + 1]};
                *(float2*)&out[(size_t)row * Nout + col]       = v0;
                *(float2*)&out[(size_t)(row + 8) * Nout + col] = v1;
            }
        }
    }
}

// ============================================================
// gate final reduce: gate[m] = sum of 4 column partials + b2
// ============================================================
__global__ __launch_bounds__(256) void k_gate_final(const float* __restrict__ b2) {
    const int m = blockIdx.x * 256 + threadIdx.x;
    g_gate[m] = g_gpart[0][m] + g_gpart[1][m] + g_gpart[2][m] + g_gpart[3][m] + b2[0];
}

// ============================================================
// per-(b,block) masked softmax + ct-mod + pooling
// ============================================================
__global__ __launch_bounds__(256) void k_pool(const float* __restrict__ X,
                                              const int* __restrict__ bids,
                                              const unsigned char* __restrict__ pad,
                                              const int* __restrict__ ctype,
                                              const float* __restrict__ ct_emb) {
    const int b = blockIdx.y, k = blockIdx.x;
    const int tid = threadIdx.x;
    __shared__ int   s_idx[N_];
    __shared__ float s_w[N_];
    __shared__ float red[256];
    __shared__ int   s_cnt;
    if (tid == 0) s_cnt = 0;
    const int base = b * N_;

    float mx = -INFINITY;
    for (int n = tid; n < N_; n += 256) {
        if (bids[base + n] == k && pad[base + n] == 0)
            mx = fmaxf(mx, g_gate[base + n]);
    }
    red[tid] = mx;
    __syncthreads();
    for (int st = 128; st; st >>= 1) {
        if (tid < st) red[tid] = fmaxf(red[tid], red[tid + st]);
        __syncthreads();
    }
    float m = red[0];
    __syncthreads();
    if (!isfinite(m)) m = 0.f;

    float se = 0.f;
    for (int n = tid; n < N_; n += 256) {
        if (bids[base + n] == k && pad[base + n] == 0) {
            float e = expf(g_gate[base + n] - m);
            se += e;
            int p = atomicAdd(&s_cnt, 1);
            s_idx[p] = n;
            s_w[p]   = e;
        }
    }
    red[tid] = se;
    __syncthreads();
    for (int st = 128; st; st >>= 1) {
        if (tid < st) red[tid] += red[tid + st];
        __syncthreads();
    }
    const float denom = red[0];
    __syncthreads();

    const float factor = 1.f + 0.1f * ct_emb[ctype[b] * NB_ + k];
    const float inv = (denom > 0.f) ? factor / fmaxf(denom, 1e-30f) : 0.f;
    const int cnt = s_cnt;

    float a0 = 0.f, a1 = 0.f, a2 = 0.f, a3 = 0.f;
    for (int i = 0; i < cnt; ++i) {
        const float w = s_w[i] * inv;
        const float* xr = X + ((size_t)base + s_idx[i]) * H_;
        a0 += w * xr[tid];
        a1 += w * xr[tid + 256];
        a2 += w * xr[tid + 512];
        a3 += w * xr[tid + 768];
    }
    float* pr = g_pooled + (size_t)(b * NB_ + k) * H_;
    pr[tid]       = a0;
    pr[tid + 256] = a1;
    pr[tid + 512] = a2;
    pr[tid + 768] = a3;
    if (tid == 0) g_hasb[b * NB_ + k] = (cnt > 0) ? 1.f : 0.f;
}

// ============================================================
// LayerNorm + ELU + present mask
// ============================================================
__global__ __launch_bounds__(256) void k_ln(const float* __restrict__ ln_g,
                                            const float* __restrict__ ln_b,
                                            float* __restrict__ out,
                                            int out_size) {
    const int row = blockIdx.x;
    const int tid = threadIdx.x;
    __shared__ float red[256];
    __shared__ float sh_mu, sh_r;
    __shared__ int sh_present;

    float4 v = ((const float4*)(g_y + (size_t)row * H_))[tid];
    red[tid] = v.x + v.y + v.z + v.w;
    __syncthreads();
    for (int st = 128; st; st >>= 1) {
        if (tid < st) red[tid] += red[tid + st];
        __syncthreads();
    }
    if (tid == 0) sh_mu = red[0] * (1.f / H_);
    __syncthreads();
    const float mu = sh_mu;
    const float dx = v.x - mu, dy = v.y - mu, dz = v.z - mu, dw = v.w - mu;
    red[tid] = dx * dx + dy * dy + dz * dz + dw * dw;
    __syncthreads();
    for (int st = 128; st; st >>= 1) {
        if (tid < st) red[tid] += red[tid + st];
        __syncthreads();
    }
    if (tid == 0) {
        sh_r = rsqrtf(red[0] * (1.f / H_) + 1e-5f);
        const int k = row & (NB_ - 1);
        int p = 0;
        for (int bb = 0; bb < B_; ++bb) p |= (g_hasb[bb * NB_ + k] != 0.f);
        sh_present = p;
    }
    __syncthreads();
    const float r = sh_r;
    const int present = sh_present;

    float4 g = ((const float4*)ln_g)[tid];
    float4 be = ((const float4*)ln_b)[tid];
    float4 o;
    o.x = dx * r * g.x + be.x;
    o.y = dy * r * g.y + be.y;
    o.z = dz * r * g.z + be.z;
    o.w = dw * r * g.w + be.w;
    o.x = (o.x > 0.f) ? o.x : expm1f(o.x);
    o.y = (o.y > 0.f) ? o.y : expm1f(o.y);
    o.z = (o.z > 0.f) ? o.z : expm1f(o.z);
    o.w = (o.w > 0.f) ? o.w : expm1f(o.w);
    if (!present) { o.x = 0.f; o.y = 0.f; o.z = 0.f; o.w = 0.f; }
    ((float4*)(out + (size_t)row * H_))[tid] = o;

    if (tid == 0 && out_size >= B_ * NB_ * H_ + B_ * NB_)
        out[B_ * NB_ * H_ + row] = g_hasb[row];
}

// ============================================================
extern "C" void kernel_launch(void* const* d_in, const int* in_sizes, int n_in,
                              void* d_out, int out_size) {
    const float* x       = (const float*)d_in[0];
    const int*   ctype   = (const int*)d_in[1];
    const int*   bids    = (const int*)d_in[2];
    const unsigned char* pad = (const unsigned char*)d_in[3];
    const float* W1      = (const float*)d_in[4];
    const float* b1      = (const float*)d_in[5];
    const float* W2      = (const float*)d_in[6];
    const float* b2      = (const float*)d_in[7];
    const float* ct_emb  = (const float*)d_in[8];
    const float* Wp      = (const float*)d_in[9];
    const float* bp      = (const float*)d_in[10];
    const float* ln_g    = (const float*)d_in[11];
    const float* ln_b    = (const float*)d_in[12];
    float* out = (float*)d_out;

    cudaFuncSetAttribute(k_mma<0>, cudaFuncAttributeMaxDynamicSharedMemorySize, SMEM_DYN);
    cudaFuncSetAttribute(k_mma<1>, cudaFuncAttributeMaxDynamicSharedMemorySize, SMEM_DYN);

    hf *ah, *w1h, *w1l, *ph, *wph, *wpl;
    float *pooled, *ybuf, *gpart;
    cudaGetSymbolAddress((void**)&ah,   g_ah);
    cudaGetSymbolAddress((void**)&w1h,  g_w1h);
    cudaGetSymbolAddress((void**)&w1l,  g_w1l);
    cudaGetSymbolAddress((void**)&ph,   g_ph);
    cudaGetSymbolAddress((void**)&wph,  g_wph);
    cudaGetSymbolAddress((void**)&wpl,  g_wpl);
    cudaGetSymbolAddress((void**)&pooled, g_pooled);
    cudaGetSymbolAddress((void**)&ybuf, g_y);
    cudaGetSymbolAddress((void**)&gpart, g_gpart);

    // gate MLP: gemm1 with fused tanh + W2 dot (h never materialized)
    k_cvt_h<<<(size_t)M_ * H_ / 4 / 256, 256>>>(x, ah);
    k_split_wt<<<dim3(H_ / 32, H2_ / 32), 256>>>(W1, w1h, w1l, H_, H2_);
    k_mma<0><<<dim3(H2_ / 128, M_ / 128), 256, SMEM_DYN>>>(
        ah, w1h, w1l, b1, W2, nullptr, gpart, H_, H2_);
    k_gate_final<<<M_ / 256, 256>>>(b2);
    // softmax + pooling
    k_pool<<<dim3(NB_, B_), 256>>>(x, bids, pad, ctype, ct_emb);
    // projection: pooled @ Wp + bp
    k_cvt_h<<<(size_t)B_ * NB_ * H_ / 4 / 256, 256>>>(pooled, ph);
    k_split_wt<<<dim3(H_ / 32, H_ / 32), 256>>>(Wp, wph, wpl, H_, H_);
    k_mma<1><<<dim3(H_ / 128, (B_ * NB_) / 128), 256, SMEM_DYN>>>(
        ph, wph, wpl, bp, nullptr, ybuf, nullptr, H_, H_);
    // LN + ELU
    k_ln<<<B_ * NB_, 256>>>(ln_g, ln_b, out, out_size);
}

// round 17
// speedup vs baseline: 4.5802x; 1.5051x over previous
#include <cuda_runtime.h>
#include <cuda_fp16.h>
#include <cstdint>
#include <math.h>

#define B_   8
#define N_   4096
#define H_   1024
#define H2_  512
#define NB_  128
#define M_   (B_*N_)          // 32768 tokens

typedef __half hf;

// -------- scratch (device globals: allocation-free rule) --------
__device__ float g_gate[M_];
__device__ float g_gpart[4][M_];                 // per-column-CTA gate partials
__device__ float g_pooled[(size_t)B_*NB_*H_];    // 4 MB
__device__ float g_y[(size_t)B_*NB_*H_];         // 4 MB
__device__ float g_hasb[B_*NB_];

__device__ hf g_ah[(size_t)M_ * H_];             // 64 MB  x as fp16
__device__ hf g_w1h[(size_t)H2_ * H_];           // 1 MB   W1^T fp16
__device__ hf g_ph[(size_t)B_*NB_ * H_];         // 2 MB   pooled fp16
__device__ hf g_wph[(size_t)H_ * H_];            // 2 MB   Wp^T fp16

// ============================================================
// PTX helpers (sm_80-compatible; ptxas targets plain sm_103)
// ============================================================
__device__ __forceinline__ uint32_t smem_u32(const void* p) {
    uint32_t a;
    asm("{ .reg .u64 t; cvta.to.shared.u64 t, %1; cvt.u32.u64 %0, t; }" : "=r"(a) : "l"(p));
    return a;
}
#define SWZ(o) ((o) ^ (((o) >> 3) & 0x70))

__device__ __forceinline__ void cp_async16(uint32_t saddr, const void* gaddr) {
    asm volatile("cp.async.cg.shared.global [%0], [%1], 16;" :: "r"(saddr), "l"(gaddr));
}
#define CP_COMMIT() asm volatile("cp.async.commit_group;" ::: "memory")

__device__ __forceinline__ void ldsm4(uint32_t* r, uint32_t a) {
    asm volatile("ldmatrix.sync.aligned.m8n8.x4.shared.b16 {%0,%1,%2,%3}, [%4];"
                 : "=r"(r[0]), "=r"(r[1]), "=r"(r[2]), "=r"(r[3]) : "r"(a));
}
__device__ __forceinline__ void ldsm2(uint32_t* r, uint32_t a) {
    asm volatile("ldmatrix.sync.aligned.m8n8.x2.shared.b16 {%0,%1}, [%2];"
                 : "=r"(r[0]), "=r"(r[1]) : "r"(a));
}
__device__ __forceinline__ void mma16816(float* c, const uint32_t* a, const uint32_t* b) {
    asm volatile(
        "mma.sync.aligned.m16n8k16.row.col.f32.f16.f16.f32 "
        "{%0,%1,%2,%3}, {%4,%5,%6,%7}, {%8,%9}, {%0,%1,%2,%3};"
        : "+f"(c[0]), "+f"(c[1]), "+f"(c[2]), "+f"(c[3])
        : "r"(a[0]), "r"(a[1]), "r"(a[2]), "r"(a[3]), "r"(b[0]), "r"(b[1]));
}

// ============================================================
// Conversion kernels
// ============================================================
// fp32 -> fp16, vectorized
__global__ __launch_bounds__(256) void k_cvt_h(const float* __restrict__ X,
                                               hf* __restrict__ out) {
    size_t i = (size_t)blockIdx.x * 256 + threadIdx.x;   // float4 index
    float4 v = ((const float4*)X)[i];
    __half2 h0 = __floats2half2_rn(v.x, v.y);
    __half2 h1 = __floats2half2_rn(v.z, v.w);
    uint2 hp = {*(uint32_t*)&h0, *(uint32_t*)&h1};
    ((uint2*)out)[i] = hp;
}

// W [K x Nn] row-major -> T [Nn x K] fp16 (transpose + convert)
__global__ __launch_bounds__(256) void k_cvt_wt(const float* __restrict__ W,
                                                hf* __restrict__ T,
                                                int K, int Nn) {
    __shared__ float t[32][33];
    const int k0 = blockIdx.x * 32, n0 = blockIdx.y * 32;
    const int tx = threadIdx.x & 31, ty = threadIdx.x >> 5;  // 32 x 8
#pragma unroll
    for (int i = 0; i < 32; i += 8)
        t[ty + i][tx] = W[(size_t)(k0 + ty + i) * Nn + n0 + tx];
    __syncthreads();
#pragma unroll
    for (int i = 0; i < 32; i += 8)
        T[(size_t)(n0 + ty + i) * K + k0 + tx] = __float2half_rn(t[tx][ty + i]);
}

// ============================================================
// mma.sync fp16 GEMM: C[M x Nout] = A @ B^T (single term)
// CTA 128x128, K-chunk 64, stage = A(16K)+B(16K) = 32KB, 2-stage cp.async
// EPI 0: gate fusion  -> gpart[cta_n][m] = sum_n tanh(acc+b1[n])*W2[n]
// EPI 1: out = acc + bias
// ============================================================
#define STG_BYTES 32768
#define SMEM_DYN  (2 * STG_BYTES + 1024)

template <int EPI>
__global__ __launch_bounds__(256) void k_mma(const hf* __restrict__ Ah,
                                             const hf* __restrict__ Bh,
                                             const float* __restrict__ bias,
                                             const float* __restrict__ w2,
                                             float* __restrict__ out,
                                             float* __restrict__ gpart,
                                             int Ktot, int Nout) {
    extern __shared__ char smem_raw[];
    const int tid = threadIdx.x;
    const int wid = tid >> 5, lane = tid & 31;
    const int mw = wid & 1, nw = wid >> 1;        // 2 x 4 warp grid
    const int m0 = blockIdx.y * 128;
    const int n0 = blockIdx.x * 128;
    const uint32_t sbase = (smem_u32(smem_raw) + 1023u) & ~1023u;
    const int NC = Ktot >> 6;                     // K-chunks of 64

    float C[4][4][4];
#pragma unroll
    for (int mi = 0; mi < 4; ++mi)
#pragma unroll
        for (int ni = 0; ni < 4; ++ni)
#pragma unroll
            for (int q = 0; q < 4; ++q) C[mi][ni][q] = 0.f;

    // stage layout: A @ 0 (16KB), B @ 16384; rows = 128B (64 fp16)
    auto load_chunk = [&](int c, int st) {
        const uint32_t sa = sbase + (uint32_t)st * STG_BYTES;
        const int k0 = c * 64;
#pragma unroll
        for (int t = 0; t < 2; ++t) {
            const hf* src = (t == 0) ? Ah : Bh;
            const int row0 = (t == 0) ? m0 : n0;
#pragma unroll
            for (int i = 0; i < 4; ++i) {
                int id = tid + i * 256;           // 0..1023
                int r = id >> 3, g = id & 7;      // row, 16B group
                uint32_t off = (uint32_t)(r * 128 + g * 16);
                cp_async16(sa + (uint32_t)t * 16384u + SWZ(off),
                           src + (size_t)(row0 + r) * Ktot + k0 + g * 8);
            }
        }
        CP_COMMIT();
    };

    auto compute = [&](int st) {
        const uint32_t sa = sbase + (uint32_t)st * STG_BYTES;
        const uint32_t sb = sa + 16384u;
#pragma unroll
        for (int kb = 0; kb < 64; kb += 16) {
            uint32_t Af[4][4];
#pragma unroll
            for (int mi = 0; mi < 4; ++mi) {
                int row = mw * 64 + mi * 16 + (lane & 15);
                uint32_t coln = (uint32_t)((kb + (lane >> 4) * 8) * 2);
                ldsm4(Af[mi], sa + row * 128 + (coln ^ ((row & 7) << 4)));
            }
            uint32_t Bf[4][2];
#pragma unroll
            for (int ni = 0; ni < 4; ++ni) {
                int row = nw * 32 + ni * 8 + (lane & 7);
                uint32_t coln = (uint32_t)((kb + ((lane >> 3) & 1) * 8) * 2);
                ldsm2(Bf[ni], sb + row * 128 + (coln ^ ((row & 7) << 4)));
            }
#pragma unroll
            for (int mi = 0; mi < 4; ++mi)
#pragma unroll
                for (int ni = 0; ni < 4; ++ni)
                    mma16816(C[mi][ni], Af[mi], Bf[ni]);
        }
    };

    load_chunk(0, 0);
    if (NC > 1) load_chunk(1, 1);

    for (int c = 0; c < NC; ++c) {
        if (c + 1 < NC) asm volatile("cp.async.wait_group 1;" ::: "memory");
        else            asm volatile("cp.async.wait_group 0;" ::: "memory");
        __syncthreads();
        compute(c & 1);
        __syncthreads();
        if (c + 2 < NC) load_chunk(c + 2, c & 1);
    }

    if (EPI == 0) {
        // gate fusion: per-row partial dot of tanh(acc+b1) with W2
        float* gp = (float*)smem_raw;     // [4][128], pipeline smem is done
        const int cbase = n0 + nw * 32 + 2 * (lane & 3);
        float w2v[4][2], b1v[4][2];
#pragma unroll
        for (int ni = 0; ni < 4; ++ni) {
            w2v[ni][0] = w2[cbase + ni * 8];
            w2v[ni][1] = w2[cbase + ni * 8 + 1];
            b1v[ni][0] = bias[cbase + ni * 8];
            b1v[ni][1] = bias[cbase + ni * 8 + 1];
        }
#pragma unroll
        for (int mi = 0; mi < 4; ++mi) {
            float a = 0.f, b = 0.f;
#pragma unroll
            for (int ni = 0; ni < 4; ++ni) {
                a += tanhf(C[mi][ni][0] + b1v[ni][0]) * w2v[ni][0];
                a += tanhf(C[mi][ni][1] + b1v[ni][1]) * w2v[ni][1];
                b += tanhf(C[mi][ni][2] + b1v[ni][0]) * w2v[ni][0];
                b += tanhf(C[mi][ni][3] + b1v[ni][1]) * w2v[ni][1];
            }
            a += __shfl_xor_sync(0xFFFFFFFFu, a, 1);
            a += __shfl_xor_sync(0xFFFFFFFFu, a, 2);
            b += __shfl_xor_sync(0xFFFFFFFFu, b, 1);
            b += __shfl_xor_sync(0xFFFFFFFFu, b, 2);
            if ((lane & 3) == 0) {
                int ml = mw * 64 + mi * 16 + (lane >> 2);
                gp[nw * 128 + ml]     = a;
                gp[nw * 128 + ml + 8] = b;
            }
        }
        __syncthreads();
        if (tid < 128) {
            float s = gp[tid] + gp[128 + tid] + gp[256 + tid] + gp[384 + tid];
            gpart[(size_t)blockIdx.x * M_ + m0 + tid] = s;
        }
    } else {
        // plain bias epilogue -> out
#pragma unroll
        for (int mi = 0; mi < 4; ++mi) {
            const int row = m0 + mw * 64 + mi * 16 + (lane >> 2);
#pragma unroll
            for (int ni = 0; ni < 4; ++ni) {
                const int col = n0 + nw * 32 + ni * 8 + 2 * (lane & 3);
                float2 v0 = {C[mi][ni][0] + bias[col], C[mi][ni][1] + bias[col + 1]};
                float2 v1 = {C[mi][ni][2] + bias[col], C[mi][ni][3] + bias[col + 1]};
                *(float2*)&out[(size_t)row * Nout + col]       = v0;
                *(float2*)&out[(size_t)(row + 8) * Nout + col] = v1;
            }
        }
    }
}

// ============================================================
// gate final reduce: gate[m] = sum of 4 column partials + b2
// ============================================================
__global__ __launch_bounds__(256) void k_gate_final(const float* __restrict__ b2) {
    const int m = blockIdx.x * 256 + threadIdx.x;
    g_gate[m] = g_gpart[0][m] + g_gpart[1][m] + g_gpart[2][m] + g_gpart[3][m] + b2[0];
}

// ============================================================
// per-(b,block) masked softmax + ct-mod + pooling
// ============================================================
__global__ __launch_bounds__(256) void k_pool(const float* __restrict__ X,
                                              const int* __restrict__ bids,
                                              const unsigned char* __restrict__ pad,
                                              const int* __restrict__ ctype,
                                              const float* __restrict__ ct_emb) {
    const int b = blockIdx.y, k = blockIdx.x;
    const int tid = threadIdx.x;
    __shared__ int   s_idx[N_];
    __shared__ float s_w[N_];
    __shared__ float red[256];
    __shared__ int   s_cnt;
    if (tid == 0) s_cnt = 0;
    const int base = b * N_;

    float mx = -INFINITY;
    for (int n = tid; n < N_; n += 256) {
        if (bids[base + n] == k && pad[base + n] == 0)
            mx = fmaxf(mx, g_gate[base + n]);
    }
    red[tid] = mx;
    __syncthreads();
    for (int st = 128; st; st >>= 1) {
        if (tid < st) red[tid] = fmaxf(red[tid], red[tid + st]);
        __syncthreads();
    }
    float m = red[0];
    __syncthreads();
    if (!isfinite(m)) m = 0.f;

    float se = 0.f;
    for (int n = tid; n < N_; n += 256) {
        if (bids[base + n] == k && pad[base + n] == 0) {
            float e = expf(g_gate[base + n] - m);
            se += e;
            int p = atomicAdd(&s_cnt, 1);
            s_idx[p] = n;
            s_w[p]   = e;
        }
    }
    red[tid] = se;
    __syncthreads();
    for (int st = 128; st; st >>= 1) {
        if (tid < st) red[tid] += red[tid + st];
        __syncthreads();
    }
    const float denom = red[0];
    __syncthreads();

    const float factor = 1.f + 0.1f * ct_emb[ctype[b] * NB_ + k];
    const float inv = (denom > 0.f) ? factor / fmaxf(denom, 1e-30f) : 0.f;
    const int cnt = s_cnt;

    float a0 = 0.f, a1 = 0.f, a2 = 0.f, a3 = 0.f;
    for (int i = 0; i < cnt; ++i) {
        const float w = s_w[i] * inv;
        const float* xr = X + ((size_t)base + s_idx[i]) * H_;
        a0 += w * xr[tid];
        a1 += w * xr[tid + 256];
        a2 += w * xr[tid + 512];
        a3 += w * xr[tid + 768];
    }
    float* pr = g_pooled + (size_t)(b * NB_ + k) * H_;
    pr[tid]       = a0;
    pr[tid + 256] = a1;
    pr[tid + 512] = a2;
    pr[tid + 768] = a3;
    if (tid == 0) g_hasb[b * NB_ + k] = (cnt > 0) ? 1.f : 0.f;
}

// ============================================================
// LayerNorm + ELU + present mask
// ============================================================
__global__ __launch_bounds__(256) void k_ln(const float* __restrict__ ln_g,
                                            const float* __restrict__ ln_b,
                                            float* __restrict__ out,
                                            int out_size) {
    const int row = blockIdx.x;
    const int tid = threadIdx.x;
    __shared__ float red[256];
    __shared__ float sh_mu, sh_r;
    __shared__ int sh_present;

    float4 v = ((const float4*)(g_y + (size_t)row * H_))[tid];
    red[tid] = v.x + v.y + v.z + v.w;
    __syncthreads();
    for (int st = 128; st; st >>= 1) {
        if (tid < st) red[tid] += red[tid + st];
        __syncthreads();
    }
    if (tid == 0) sh_mu = red[0] * (1.f / H_);
    __syncthreads();
    const float mu = sh_mu;
    const float dx = v.x - mu, dy = v.y - mu, dz = v.z - mu, dw = v.w - mu;
    red[tid] = dx * dx + dy * dy + dz * dz + dw * dw;
    __syncthreads();
    for (int st = 128; st; st >>= 1) {
        if (tid < st) red[tid] += red[tid + st];
        __syncthreads();
    }
    if (tid == 0) {
        sh_r = rsqrtf(red[0] * (1.f / H_) + 1e-5f);
        const int k = row & (NB_ - 1);
        int p = 0;
        for (int bb = 0; bb < B_; ++bb) p |= (g_hasb[bb * NB_ + k] != 0.f);
        sh_present = p;
    }
    __syncthreads();
    const float r = sh_r;
    const int present = sh_present;

    float4 g = ((const float4*)ln_g)[tid];
    float4 be = ((const float4*)ln_b)[tid];
    float4 o;
    o.x = dx * r * g.x + be.x;
    o.y = dy * r * g.y + be.y;
    o.z = dz * r * g.z + be.z;
    o.w = dw * r * g.w + be.w;
    o.x = (o.x > 0.f) ? o.x : expm1f(o.x);
    o.y = (o.y > 0.f) ? o.y : expm1f(o.y);
    o.z = (o.z > 0.f) ? o.z : expm1f(o.z);
    o.w = (o.w > 0.f) ? o.w : expm1f(o.w);
    if (!present) { o.x = 0.f; o.y = 0.f; o.z = 0.f; o.w = 0.f; }
    ((float4*)(out + (size_t)row * H_))[tid] = o;

    if (tid == 0 && out_size >= B_ * NB_ * H_ + B_ * NB_)
        out[B_ * NB_ * H_ + row] = g_hasb[row];
}

// ============================================================
extern "C" void kernel_launch(void* const* d_in, const int* in_sizes, int n_in,
                              void* d_out, int out_size) {
    const float* x       = (const float*)d_in[0];
    const int*   ctype   = (const int*)d_in[1];
    const int*   bids    = (const int*)d_in[2];
    const unsigned char* pad = (const unsigned char*)d_in[3];
    const float* W1      = (const float*)d_in[4];
    const float* b1      = (const float*)d_in[5];
    const float* W2      = (const float*)d_in[6];
    const float* b2      = (const float*)d_in[7];
    const float* ct_emb  = (const float*)d_in[8];
    const float* Wp      = (const float*)d_in[9];
    const float* bp      = (const float*)d_in[10];
    const float* ln_g    = (const float*)d_in[11];
    const float* ln_b    = (const float*)d_in[12];
    float* out = (float*)d_out;

    cudaFuncSetAttribute(k_mma<0>, cudaFuncAttributeMaxDynamicSharedMemorySize, SMEM_DYN);
    cudaFuncSetAttribute(k_mma<1>, cudaFuncAttributeMaxDynamicSharedMemorySize, SMEM_DYN);

    hf *ah, *w1h, *ph, *wph;
    float *pooled, *ybuf, *gpart;
    cudaGetSymbolAddress((void**)&ah,   g_ah);
    cudaGetSymbolAddress((void**)&w1h,  g_w1h);
    cudaGetSymbolAddress((void**)&ph,   g_ph);
    cudaGetSymbolAddress((void**)&wph,  g_wph);
    cudaGetSymbolAddress((void**)&pooled, g_pooled);
    cudaGetSymbolAddress((void**)&ybuf, g_y);
    cudaGetSymbolAddress((void**)&gpart, g_gpart);

    // gate MLP: gemm1 with fused tanh + W2 dot (h never materialized)
    k_cvt_h<<<(size_t)M_ * H_ / 4 / 256, 256>>>(x, ah);
    k_cvt_wt<<<dim3(H_ / 32, H2_ / 32), 256>>>(W1, w1h, H_, H2_);
    k_mma<0><<<dim3(H2_ / 128, M_ / 128), 256, SMEM_DYN>>>(
        ah, w1h, b1, W2, nullptr, gpart, H_, H2_);
    k_gate_final<<<M_ / 256, 256>>>(b2);
    // softmax + pooling
    k_pool<<<dim3(NB_, B_), 256>>>(x, bids, pad, ctype, ct_emb);
    // projection: pooled @ Wp + bp
    k_cvt_h<<<(size_t)B_ * NB_ * H_ / 4 / 256, 256>>>(pooled, ph);
    k_cvt_wt<<<dim3(H_ / 32, H_ / 32), 256>>>(Wp, wph, H_, H_);
    k_mma<1><<<dim3(H_ / 128, (B_ * NB_) / 128), 256, SMEM_DYN>>>(
        ph, wph, bp, nullptr, ybuf, nullptr, H_, H_);
    // LN + ELU
    k_ln<<<B_ * NB_, 256>>>(ln_g, ln_b, out, out_size);
}